// round 1
// baseline (speedup 1.0000x reference)
#include <cuda_runtime.h>
#include <cuda_bf16.h>
#include <cstdint>

#define BH 32
#define Lq 1024
#define Dd 64

// Scratch (allocation-free rule: __device__ globals).
// Xs = (X @ W1^T + b1) * w2   [BH*L, D]
// Yf = (Y @ W1^T + b1)        [BH*L, D]
__device__ float g_Xs[BH * Lq * Dd];
__device__ float g_Yf[BH * Lq * Dd];

// ---------------------------------------------------------------------------
// Stage 1: row-wise projection. grid = (BH*L/64, 2); block = 256.
// blockIdx.y == 0 -> X path (fold w2), == 1 -> Y path.
// ---------------------------------------------------------------------------
__global__ __launch_bounds__(256) void stage1_kernel(
    const float* __restrict__ X, const float* __restrict__ Y,
    const float* __restrict__ W1, const float* __restrict__ b1,
    const float* __restrict__ w2)
{
    __shared__ float Wt[64][66];   // Wt[k][d] = W1[d][k]
    __shared__ float In[64][68];   // input tile, padded for conflict-free broadcast reads
    __shared__ float sb1[64], sw2[64];

    const int tid = threadIdx.x;
    const bool isX = (blockIdx.y == 0);
    const float* __restrict__ src = isX ? X : Y;
    float* __restrict__ dst = isX ? g_Xs : g_Yf;
    const int rowBase = blockIdx.x * 64;

    // W1 transposed into smem
    #pragma unroll
    for (int i = 0; i < 16; ++i) {
        int idx = tid + i * 256;         // 4096 elements
        int d = idx >> 6, k = idx & 63;
        Wt[k][d] = W1[idx];
    }
    if (tid < 64) { sb1[tid] = b1[tid]; sw2[tid] = w2[tid]; }

    // input tile 64x64 via float4
    const float4* src4 = (const float4*)(src + (size_t)rowBase * 64);
    #pragma unroll
    for (int i = 0; i < 4; ++i) {
        int idx = tid + i * 256;         // 1024 float4
        int m = idx >> 4, kq = idx & 15;
        float4 v = src4[idx];
        *(float4*)&In[m][kq * 4] = v;
    }
    __syncthreads();

    const int m  = tid >> 2;
    const int d0 = (tid & 3) * 16;

    unsigned long long acc[8];
    #pragma unroll
    for (int i = 0; i < 8; ++i) acc[i] = 0ull;

    #pragma unroll 8
    for (int k = 0; k < 64; ++k) {
        float xv = In[m][k];
        unsigned long long xx;
        asm("mov.b64 %0, {%1, %1};" : "=l"(xx) : "f"(xv));
        const unsigned long long* wrow = (const unsigned long long*)&Wt[k][d0];
        #pragma unroll
        for (int i = 0; i < 8; ++i)
            asm("fma.rn.f32x2 %0, %1, %2, %0;" : "+l"(acc[i]) : "l"(xx), "l"(wrow[i]));
    }

    float* out = dst + (size_t)(rowBase + m) * 64 + d0;
    #pragma unroll
    for (int i = 0; i < 8; ++i) {
        float lo, hi;
        asm("mov.b64 {%0, %1}, %2;" : "=f"(lo), "=f"(hi) : "l"(acc[i]));
        int d = d0 + 2 * i;
        lo += sb1[d];
        hi += sb1[d + 1];
        if (isX) { lo *= sw2[d]; hi *= sw2[d + 1]; }
        out[2 * i]     = lo;
        out[2 * i + 1] = hi;
    }
}

// ---------------------------------------------------------------------------
// Stage 2: per-batch GEMM  scores = Xs @ Yf^T (+b2, relu).
// grid = (L/128, L/128, BH) = (8, 8, 32); block = 256; dyn smem = 64 KB.
// Tile 128(M) x 128(N), K = 64 (full). 8x8 micro-tile / thread, packed f32x2.
// ---------------------------------------------------------------------------
__global__ __launch_bounds__(256, 2) void stage2_kernel(
    const float* __restrict__ b2p, float* __restrict__ out)
{
    extern __shared__ float smem[];
    float* As = smem;            // [128][64]  m-major (a-loads are warp-broadcast)
    float* Bs = smem + 128 * 64; // [64][128]  k-major (b-loads are native 64-bit pairs)

    const int tid   = threadIdx.x;
    const int bh    = blockIdx.z;
    const int mBase = blockIdx.y * 128;
    const int nBase = blockIdx.x * 128;

    const float* __restrict__ Ag = g_Xs + (size_t)(bh * Lq + mBase) * 64;
    const float* __restrict__ Bg = g_Yf + (size_t)(bh * Lq + nBase) * 64;

    // A: direct float4 copy (coalesced, conflict-free)
    {
        const float4* a4 = (const float4*)Ag;
        float4* s4 = (float4*)As;
        #pragma unroll
        for (int i = 0; i < 8; ++i)
            s4[tid + i * 256] = a4[tid + i * 256];
    }
    // B: transpose into k-major. Thread: kq = tid>>4 (k-quad), n0 = tid&15.
    // smem stores: lanes span consecutive n -> conflict-free.
    {
        const int kq = tid >> 4;
        const int n0 = tid & 15;
        #pragma unroll
        for (int i = 0; i < 8; ++i) {
            int n = n0 + i * 16;
            float4 v = *(const float4*)(Bg + (size_t)n * 64 + kq * 4);
            Bs[(kq * 4 + 0) * 128 + n] = v.x;
            Bs[(kq * 4 + 1) * 128 + n] = v.y;
            Bs[(kq * 4 + 2) * 128 + n] = v.z;
            Bs[(kq * 4 + 3) * 128 + n] = v.w;
        }
    }
    __syncthreads();

    const int tx = tid & 15;
    const int ty = tid >> 4;
    const int m0 = ty * 8;
    const int n0 = tx * 8;

    unsigned long long acc[8][4];
    #pragma unroll
    for (int i = 0; i < 8; ++i)
        #pragma unroll
        for (int j = 0; j < 4; ++j) acc[i][j] = 0ull;

    #pragma unroll 8
    for (int k = 0; k < 64; ++k) {
        const unsigned long long* brow =
            (const unsigned long long*)(Bs + k * 128 + n0);
        unsigned long long b[4];
        #pragma unroll
        for (int j = 0; j < 4; ++j) b[j] = brow[j];
        #pragma unroll
        for (int i = 0; i < 8; ++i) {
            float av = As[(m0 + i) * 64 + k];
            unsigned long long aa;
            asm("mov.b64 %0, {%1, %1};" : "=l"(aa) : "f"(av));
            #pragma unroll
            for (int j = 0; j < 4; ++j)
                asm("fma.rn.f32x2 %0, %1, %2, %0;"
                    : "+l"(acc[i][j]) : "l"(aa), "l"(b[j]));
        }
    }

    const float b2 = *b2p;
    #pragma unroll
    for (int i = 0; i < 8; ++i) {
        float r[8];
        #pragma unroll
        for (int j = 0; j < 4; ++j) {
            float lo, hi;
            asm("mov.b64 {%0, %1}, %2;" : "=f"(lo), "=f"(hi) : "l"(acc[i][j]));
            lo += b2; hi += b2;
            r[2 * j]     = fmaxf(lo, 0.0f);
            r[2 * j + 1] = fmaxf(hi, 0.0f);
        }
        float4* o4 = (float4*)(out +
            (size_t)(bh * Lq + mBase + m0 + i) * Lq + nBase + n0);
        o4[0] = make_float4(r[0], r[1], r[2], r[3]);
        o4[1] = make_float4(r[4], r[5], r[6], r[7]);
    }
}

// ---------------------------------------------------------------------------
extern "C" void kernel_launch(void* const* d_in, const int* in_sizes, int n_in,
                              void* d_out, int out_size)
{
    const float* X  = (const float*)d_in[0];
    const float* Y  = (const float*)d_in[1];
    const float* W1 = (const float*)d_in[2];
    const float* b1 = (const float*)d_in[3];
    const float* w2 = (const float*)d_in[4];
    const float* b2 = (const float*)d_in[5];
    float* out = (float*)d_out;

    stage1_kernel<<<dim3(BH * Lq / 64, 2, 1), 256>>>(X, Y, W1, b1, w2);

    cudaFuncSetAttribute(stage2_kernel,
                         cudaFuncAttributeMaxDynamicSharedMemorySize, 64 * 1024);
    stage2_kernel<<<dim3(8, 8, BH), 256, 64 * 1024>>>(b2, out);
}

// round 3
// speedup vs baseline: 2.0666x; 2.0666x over previous
#include <cuda_runtime.h>
#include <cuda_bf16.h>
#include <cstdint>

#define BH 32
#define Lq 1024
#define Dd 64

// Scratch: hi/lo bf16 split of projected activations.
//   Xs = (X @ W1^T + b1) * w2  -> g_Xhi/g_Xlo ;  Yf = (Y @ W1^T + b1) -> g_Yhi/g_Ylo
__device__ __nv_bfloat16 g_Xhi[BH * Lq * Dd];
__device__ __nv_bfloat16 g_Xlo[BH * Lq * Dd];
__device__ __nv_bfloat16 g_Yhi[BH * Lq * Dd];
__device__ __nv_bfloat16 g_Ylo[BH * Lq * Dd];

// ---------------------------------------------------------------------------
// Stage 1: projection + hi/lo bf16 split. 128 rows / CTA, 2 rows / thread.
// grid = (BH*L/128, 2); block = 256; dyn smem = 52224 B.
// ---------------------------------------------------------------------------
__global__ __launch_bounds__(256) void stage1_kernel(
    const float* __restrict__ X, const float* __restrict__ Y,
    const float* __restrict__ W1, const float* __restrict__ b1,
    const float* __restrict__ w2)
{
    extern __shared__ float s1[];
    float* Wt  = s1;                   // [64][66]  Wt[k][d] = W1[d][k]
    float* In  = s1 + 64 * 66;         // [128][68]
    float* sb1 = In + 128 * 68;        // [64]
    float* sw2 = sb1 + 64;             // [64]

    const int tid = threadIdx.x;
    const bool isX = (blockIdx.y == 0);
    const float* __restrict__ src = isX ? X : Y;
    __nv_bfloat16* __restrict__ dhi = isX ? g_Xhi : g_Yhi;
    __nv_bfloat16* __restrict__ dlo = isX ? g_Xlo : g_Ylo;
    const int rowBase = blockIdx.x * 128;

    #pragma unroll
    for (int i = 0; i < 16; ++i) {
        int idx = tid + i * 256;                 // 4096 W1 elements
        int d = idx >> 6, k = idx & 63;
        Wt[k * 66 + d] = W1[idx];
    }
    if (tid < 64) { sb1[tid] = b1[tid]; sw2[tid] = w2[tid]; }

    const float4* src4 = (const float4*)(src + (size_t)rowBase * 64);
    #pragma unroll
    for (int i = 0; i < 8; ++i) {
        int idx = tid + i * 256;                 // 2048 float4 = 128x64
        int m = idx >> 4, kq = idx & 15;
        *(float4*)&In[m * 68 + kq * 4] = src4[idx];
    }
    __syncthreads();

    const int m  = tid >> 2;                     // 0..63 (rows m and m+64)
    const int d0 = (tid & 3) * 16;

    unsigned long long acc0[8], acc1[8];
    #pragma unroll
    for (int i = 0; i < 8; ++i) { acc0[i] = 0ull; acc1[i] = 0ull; }

    #pragma unroll 4
    for (int k = 0; k < 64; ++k) {
        float x0 = In[m * 68 + k];
        float x1 = In[(m + 64) * 68 + k];
        unsigned long long xx0, xx1;
        asm("mov.b64 %0, {%1, %1};" : "=l"(xx0) : "f"(x0));
        asm("mov.b64 %0, {%1, %1};" : "=l"(xx1) : "f"(x1));
        const unsigned long long* wrow = (const unsigned long long*)&Wt[k * 66 + d0];
        #pragma unroll
        for (int i = 0; i < 8; ++i) {
            unsigned long long w = wrow[i];
            asm("fma.rn.f32x2 %0, %1, %2, %0;" : "+l"(acc0[i]) : "l"(xx0), "l"(w));
            asm("fma.rn.f32x2 %0, %1, %2, %0;" : "+l"(acc1[i]) : "l"(xx1), "l"(w));
        }
    }

    #pragma unroll
    for (int r = 0; r < 2; ++r) {
        const unsigned long long* acc = r ? acc1 : acc0;
        union { __nv_bfloat16 h[16]; uint4 u[2]; } ph, pl;
        #pragma unroll
        for (int i = 0; i < 8; ++i) {
            float lo, hi;
            asm("mov.b64 {%0, %1}, %2;" : "=f"(lo), "=f"(hi) : "l"(acc[i]));
            int d = d0 + 2 * i;
            float v0 = lo + sb1[d];
            float v1 = hi + sb1[d + 1];
            if (isX) { v0 *= sw2[d]; v1 *= sw2[d + 1]; }
            __nv_bfloat16 h0 = __float2bfloat16(v0);
            __nv_bfloat16 h1 = __float2bfloat16(v1);
            ph.h[2 * i]     = h0;
            ph.h[2 * i + 1] = h1;
            pl.h[2 * i]     = __float2bfloat16(v0 - __bfloat162float(h0));
            pl.h[2 * i + 1] = __float2bfloat16(v1 - __bfloat162float(h1));
        }
        size_t eoff = (size_t)(rowBase + m + r * 64) * 64 + d0;   // 16B aligned
        uint4* oh = (uint4*)(dhi + eoff);
        uint4* ol = (uint4*)(dlo + eoff);
        oh[0] = ph.u[0]; oh[1] = ph.u[1];
        ol[0] = pl.u[0]; ol[1] = pl.u[1];
    }
}

// ---------------------------------------------------------------------------
// Stage 2: mma.sync (HMMA) bf16 split-precision GEMM.
// grid = (8, 8, 32), block = 256 (8 warps, 64x32 warp tile), smem = 72 KB.
// D = relu( Ahi.Bhi^T + Ahi.Blo^T + Alo.Bhi^T + b2 )
// Tiles padded to stride 72 bf16 -> all fragment LDS conflict-free.
// ---------------------------------------------------------------------------
#define SA 72

__device__ __forceinline__ uint32_t fr(const __nv_bfloat16* t, int row, int k) {
    return *(const uint32_t*)(t + row * SA + k);   // 2 bf16, 4B aligned (k even)
}

__device__ __forceinline__ void mma_bf16(float* c, const uint32_t* a, const uint32_t* b) {
    asm volatile(
        "mma.sync.aligned.m16n8k16.row.col.f32.bf16.bf16.f32 "
        "{%0,%1,%2,%3}, {%4,%5,%6,%7}, {%8,%9}, {%0,%1,%2,%3};"
        : "+f"(c[0]), "+f"(c[1]), "+f"(c[2]), "+f"(c[3])
        : "r"(a[0]), "r"(a[1]), "r"(a[2]), "r"(a[3]), "r"(b[0]), "r"(b[1]));
}

__global__ __launch_bounds__(256, 2) void stage2_mma(
    const float* __restrict__ b2p, float* __restrict__ out)
{
    extern __shared__ __nv_bfloat16 sm2[];
    __nv_bfloat16* Ahi = sm2;
    __nv_bfloat16* Alo = sm2 + 128 * SA;
    __nv_bfloat16* Bhi = sm2 + 2 * 128 * SA;
    __nv_bfloat16* Blo = sm2 + 3 * 128 * SA;

    const int tid  = threadIdx.x;
    const int bhz  = blockIdx.z;
    const int mBase = blockIdx.y * 128;
    const int nBase = blockIdx.x * 128;

    // ---- fill the four 128x64 bf16 tiles (gmem rows are 128B = 8 uint4)
    {
        const uint4* srcs[4] = {
            (const uint4*)(g_Xhi + (size_t)(bhz * Lq + mBase) * 64),
            (const uint4*)(g_Xlo + (size_t)(bhz * Lq + mBase) * 64),
            (const uint4*)(g_Yhi + (size_t)(bhz * Lq + nBase) * 64),
            (const uint4*)(g_Ylo + (size_t)(bhz * Lq + nBase) * 64)};
        __nv_bfloat16* dsts[4] = {Ahi, Alo, Bhi, Blo};
        #pragma unroll
        for (int t = 0; t < 4; ++t) {
            const uint4* s = srcs[t];
            char* d = (char*)dsts[t];
            #pragma unroll
            for (int i = 0; i < 4; ++i) {
                int idx = tid + i * 256;             // 1024 chunks
                int row = idx >> 3, c = idx & 7;
                *(uint4*)(d + row * (SA * 2) + c * 16) = s[idx];
            }
        }
    }
    __syncthreads();

    const int wid  = tid >> 5, lane = tid & 31;
    const int wm   = (wid >> 2) * 64;        // warp M offset (0/64)
    const int wn   = (wid & 3) * 32;         // warp N offset (0/32/64/96)
    const int g    = lane >> 2;              // 0..7
    const int tg2  = (lane & 3) * 2;         // 0,2,4,6

    float acc[4][4][4];
    #pragma unroll
    for (int mi = 0; mi < 4; ++mi)
        #pragma unroll
        for (int ni = 0; ni < 4; ++ni)
            #pragma unroll
            for (int q = 0; q < 4; ++q) acc[mi][ni][q] = 0.0f;

    #pragma unroll
    for (int ks = 0; ks < 4; ++ks) {
        const int k0 = ks * 16;
        uint32_t a[4][4], bh[4][2], bl[4][2];
        #pragma unroll
        for (int mi = 0; mi < 4; ++mi) {
            int r = wm + mi * 16;
            a[mi][0] = fr(Ahi, r + g,     k0 + tg2);
            a[mi][1] = fr(Ahi, r + g + 8, k0 + tg2);
            a[mi][2] = fr(Ahi, r + g,     k0 + tg2 + 8);
            a[mi][3] = fr(Ahi, r + g + 8, k0 + tg2 + 8);
        }
        #pragma unroll
        for (int ni = 0; ni < 4; ++ni) {
            int n = wn + ni * 8 + g;
            bh[ni][0] = fr(Bhi, n, k0 + tg2);
            bh[ni][1] = fr(Bhi, n, k0 + tg2 + 8);
            bl[ni][0] = fr(Blo, n, k0 + tg2);
            bl[ni][1] = fr(Blo, n, k0 + tg2 + 8);
        }
        #pragma unroll
        for (int mi = 0; mi < 4; ++mi)
            #pragma unroll
            for (int ni = 0; ni < 4; ++ni) {
                mma_bf16(acc[mi][ni], a[mi], bh[ni]);
                mma_bf16(acc[mi][ni], a[mi], bl[ni]);
            }
        // reuse a[] for Alo fragments
        #pragma unroll
        for (int mi = 0; mi < 4; ++mi) {
            int r = wm + mi * 16;
            a[mi][0] = fr(Alo, r + g,     k0 + tg2);
            a[mi][1] = fr(Alo, r + g + 8, k0 + tg2);
            a[mi][2] = fr(Alo, r + g,     k0 + tg2 + 8);
            a[mi][3] = fr(Alo, r + g + 8, k0 + tg2 + 8);
        }
        #pragma unroll
        for (int mi = 0; mi < 4; ++mi)
            #pragma unroll
            for (int ni = 0; ni < 4; ++ni)
                mma_bf16(acc[mi][ni], a[mi], bh[ni]);
    }

    // ---- epilogue: +b2, relu, direct stores (8B per thread per row-half)
    const float b2 = *b2p;
    #pragma unroll
    for (int mi = 0; mi < 4; ++mi) {
        #pragma unroll
        for (int ni = 0; ni < 4; ++ni) {
            int r = mBase + wm + mi * 16 + g;
            int c = nBase + wn + ni * 8 + tg2;
            float* p = out + ((size_t)bhz * Lq + r) * Lq + c;
            float2 v0, v1;
            v0.x = fmaxf(acc[mi][ni][0] + b2, 0.0f);
            v0.y = fmaxf(acc[mi][ni][1] + b2, 0.0f);
            v1.x = fmaxf(acc[mi][ni][2] + b2, 0.0f);
            v1.y = fmaxf(acc[mi][ni][3] + b2, 0.0f);
            *(float2*)p              = v0;
            *(float2*)(p + 8 * Lq)   = v1;
        }
    }
}

// ---------------------------------------------------------------------------
extern "C" void kernel_launch(void* const* d_in, const int* in_sizes, int n_in,
                              void* d_out, int out_size)
{
    const float* X  = (const float*)d_in[0];
    const float* Y  = (const float*)d_in[1];
    const float* W1 = (const float*)d_in[2];
    const float* b1 = (const float*)d_in[3];
    const float* w2 = (const float*)d_in[4];
    const float* b2 = (const float*)d_in[5];
    float* out = (float*)d_out;

    const int s1_smem = (64 * 66 + 128 * 68 + 128) * 4;   // 52224
    cudaFuncSetAttribute(stage1_kernel,
                         cudaFuncAttributeMaxDynamicSharedMemorySize, s1_smem);
    stage1_kernel<<<dim3(BH * Lq / 128, 2, 1), 256, s1_smem>>>(X, Y, W1, b1, w2);

    const int s2_smem = 4 * 128 * SA * 2;                 // 73728
    cudaFuncSetAttribute(stage2_mma,
                         cudaFuncAttributeMaxDynamicSharedMemorySize, s2_smem);
    stage2_mma<<<dim3(8, 8, BH), 256, s2_smem>>>(b2, out);
}

// round 4
// speedup vs baseline: 3.0100x; 1.4565x over previous
#include <cuda_runtime.h>
#include <cuda_bf16.h>
#include <cstdint>

#define BH 32
#define Lq 1024
#define Dd 64

// Scratch: hi/lo bf16 split of projected activations.
__device__ __nv_bfloat16 g_Xhi[BH * Lq * Dd];
__device__ __nv_bfloat16 g_Xlo[BH * Lq * Dd];
__device__ __nv_bfloat16 g_Yhi[BH * Lq * Dd];
__device__ __nv_bfloat16 g_Ylo[BH * Lq * Dd];

// ======================== helpers ===========================
__device__ __forceinline__ uint32_t smem_u32(const void* p) {
    uint32_t a;
    asm("{ .reg .u64 t; cvta.to.shared.u64 t, %1; cvt.u32.u64 %0, t; }"
        : "=r"(a) : "l"(p));
    return a;
}
#define CP16(dst, src) \
    asm volatile("cp.async.cg.shared.global [%0], [%1], 16;" :: "r"(dst), "l"(src) : "memory")
#define CP_COMMIT() asm volatile("cp.async.commit_group;" ::: "memory")
#define CP_WAIT0()  asm volatile("cp.async.wait_group 0;" ::: "memory")

__device__ __forceinline__ void ldm4(uint32_t* r, uint32_t addr) {
    asm volatile("ldmatrix.sync.aligned.m8n8.x4.shared.b16 {%0,%1,%2,%3}, [%4];"
                 : "=r"(r[0]), "=r"(r[1]), "=r"(r[2]), "=r"(r[3]) : "r"(addr));
}
__device__ __forceinline__ void mma_bf16(float* c, const uint32_t* a, const uint32_t* b) {
    asm volatile(
        "mma.sync.aligned.m16n8k16.row.col.f32.bf16.bf16.f32 "
        "{%0,%1,%2,%3}, {%4,%5,%6,%7}, {%8,%9}, {%0,%1,%2,%3};"
        : "+f"(c[0]), "+f"(c[1]), "+f"(c[2]), "+f"(c[3])
        : "r"(a[0]), "r"(a[1]), "r"(a[2]), "r"(a[3]), "r"(b[0]), "r"(b[1]));
}
__device__ __forceinline__ uint32_t pck(__nv_bfloat16 a, __nv_bfloat16 b) {
    __nv_bfloat162 t; t.x = a; t.y = b;
    return *(uint32_t*)&t;
}
// split float4 into hi/lo bf16 packed pairs
__device__ __forceinline__ void split4(float4 v, uint2& h, uint2& l) {
    __nv_bfloat16 h0 = __float2bfloat16(v.x), h1 = __float2bfloat16(v.y);
    __nv_bfloat16 h2 = __float2bfloat16(v.z), h3 = __float2bfloat16(v.w);
    __nv_bfloat16 l0 = __float2bfloat16(v.x - __bfloat162float(h0));
    __nv_bfloat16 l1 = __float2bfloat16(v.y - __bfloat162float(h1));
    __nv_bfloat16 l2 = __float2bfloat16(v.z - __bfloat162float(h2));
    __nv_bfloat16 l3 = __float2bfloat16(v.w - __bfloat162float(h3));
    h.x = pck(h0, h1); h.y = pck(h2, h3);
    l.x = pck(l0, l1); l.y = pck(l2, l3);
}

#define SA 72   // bf16 tile stride (144 B rows: 16B-aligned, ldmatrix conflict-free)

__device__ __forceinline__ uint32_t fr(const __nv_bfloat16* t, int row, int k) {
    return *(const uint32_t*)(t + row * SA + k);
}

// ---------------------------------------------------------------------------
// Stage 1: projection as HMMA GEMM:  Out = X @ W1^T (+b1) (*w2) -> bf16 hi/lo.
// grid = (256, 2); block = 256 (8 warps, warp tile 32x32); smem ~55.8 KB.
// X and W1 each split hi/lo; 3-term product.
// ---------------------------------------------------------------------------
__global__ __launch_bounds__(256) void stage1_kernel(
    const float* __restrict__ X, const float* __restrict__ Y,
    const float* __restrict__ W1, const float* __restrict__ b1,
    const float* __restrict__ w2)
{
    extern __shared__ __nv_bfloat16 s1[];
    __nv_bfloat16* sXhi = s1;                        // [128][SA]
    __nv_bfloat16* sXlo = s1 + 128 * SA;
    __nv_bfloat16* sWhi = s1 + 2 * 128 * SA;         // [64][SA]
    __nv_bfloat16* sWlo = sWhi + 64 * SA;
    float* sb1 = (float*)(sWlo + 64 * SA);           // 55296 B offset, 4B aligned
    float* sw2 = sb1 + 64;

    const int tid = threadIdx.x;
    const bool isX = (blockIdx.y == 0);
    const float* __restrict__ src = isX ? X : Y;
    __nv_bfloat16* __restrict__ dhi = isX ? g_Xhi : g_Yhi;
    __nv_bfloat16* __restrict__ dlo = isX ? g_Xlo : g_Ylo;
    const int rowBase = blockIdx.x * 128;

    // W1 [64][64] -> hi/lo smem
    {
        const float4* w4 = (const float4*)W1;
        #pragma unroll
        for (int i = 0; i < 4; ++i) {
            int idx = tid + i * 256;                 // 1024 float4
            int d = idx >> 4, kq = idx & 15;
            uint2 h, l;
            split4(w4[idx], h, l);
            *(uint2*)&sWhi[d * SA + kq * 4] = h;
            *(uint2*)&sWlo[d * SA + kq * 4] = l;
        }
    }
    // X tile [128][64] -> hi/lo smem
    {
        const float4* x4 = (const float4*)(src + (size_t)rowBase * 64);
        #pragma unroll
        for (int i = 0; i < 8; ++i) {
            int idx = tid + i * 256;                 // 2048 float4
            int r = idx >> 4, kq = idx & 15;
            uint2 h, l;
            split4(x4[idx], h, l);
            *(uint2*)&sXhi[r * SA + kq * 4] = h;
            *(uint2*)&sXlo[r * SA + kq * 4] = l;
        }
    }
    if (tid < 64) { sb1[tid] = b1[tid]; sw2[tid] = w2[tid]; }
    __syncthreads();

    const int wid = tid >> 5, lane = tid & 31;
    const int wm = (wid >> 1) * 32;                  // 4 M groups of 32
    const int wn = (wid & 1) * 32;                   // 2 N groups of 32
    const int g = lane >> 2, tg2 = (lane & 3) * 2;

    float acc[2][4][4];
    #pragma unroll
    for (int mi = 0; mi < 2; ++mi)
        #pragma unroll
        for (int ni = 0; ni < 4; ++ni)
            #pragma unroll
            for (int q = 0; q < 4; ++q) acc[mi][ni][q] = 0.0f;

    #pragma unroll
    for (int ks = 0; ks < 4; ++ks) {
        const int k0 = ks * 16;
        uint32_t a[2][4], bh[4][2], bl[4][2];
        #pragma unroll
        for (int ni = 0; ni < 4; ++ni) {
            int n = wn + ni * 8 + g;
            bh[ni][0] = fr(sWhi, n, k0 + tg2);
            bh[ni][1] = fr(sWhi, n, k0 + tg2 + 8);
            bl[ni][0] = fr(sWlo, n, k0 + tg2);
            bl[ni][1] = fr(sWlo, n, k0 + tg2 + 8);
        }
        #pragma unroll
        for (int mi = 0; mi < 2; ++mi) {
            int r = wm + mi * 16;
            a[mi][0] = fr(sXhi, r + g,     k0 + tg2);
            a[mi][1] = fr(sXhi, r + g + 8, k0 + tg2);
            a[mi][2] = fr(sXhi, r + g,     k0 + tg2 + 8);
            a[mi][3] = fr(sXhi, r + g + 8, k0 + tg2 + 8);
        }
        #pragma unroll
        for (int mi = 0; mi < 2; ++mi)
            #pragma unroll
            for (int ni = 0; ni < 4; ++ni) {
                mma_bf16(acc[mi][ni], a[mi], bh[ni]);
                mma_bf16(acc[mi][ni], a[mi], bl[ni]);
            }
        #pragma unroll
        for (int mi = 0; mi < 2; ++mi) {
            int r = wm + mi * 16;
            a[mi][0] = fr(sXlo, r + g,     k0 + tg2);
            a[mi][1] = fr(sXlo, r + g + 8, k0 + tg2);
            a[mi][2] = fr(sXlo, r + g,     k0 + tg2 + 8);
            a[mi][3] = fr(sXlo, r + g + 8, k0 + tg2 + 8);
        }
        #pragma unroll
        for (int mi = 0; mi < 2; ++mi)
            #pragma unroll
            for (int ni = 0; ni < 4; ++ni)
                mma_bf16(acc[mi][ni], a[mi], bh[ni]);
    }

    // epilogue: +b1, (*w2 on X path), hi/lo split, 4B packed stores
    #pragma unroll
    for (int mi = 0; mi < 2; ++mi) {
        #pragma unroll
        for (int ni = 0; ni < 4; ++ni) {
            const int col = wn + ni * 8 + tg2;
            float ba = sb1[col], bb = sb1[col + 1];
            float wa = sw2[col], wb = sw2[col + 1];
            const float* c = acc[mi][ni];
            #pragma unroll
            for (int half = 0; half < 2; ++half) {
                int row = rowBase + wm + mi * 16 + g + half * 8;
                float v0 = c[2 * half + 0] + ba;
                float v1 = c[2 * half + 1] + bb;
                if (isX) { v0 *= wa; v1 *= wb; }
                __nv_bfloat16 h0 = __float2bfloat16(v0);
                __nv_bfloat16 h1 = __float2bfloat16(v1);
                __nv_bfloat16 l0 = __float2bfloat16(v0 - __bfloat162float(h0));
                __nv_bfloat16 l1 = __float2bfloat16(v1 - __bfloat162float(h1));
                size_t eoff = (size_t)row * 64 + col;
                *(uint32_t*)(dhi + eoff) = pck(h0, h1);
                *(uint32_t*)(dlo + eoff) = pck(l0, l1);
            }
        }
    }
}

// ---------------------------------------------------------------------------
// Stage 2: HMMA bf16 split GEMM with cp.async fills + ldmatrix fragments.
// grid = (8, 8, 32), block = 256 (8 warps, 64x32 warp tile), smem = 72 KB.
// D = relu( Ahi.Bhi^T + Ahi.Blo^T + Alo.Bhi^T + b2 )
// ---------------------------------------------------------------------------
#define T_AHI 0u
#define T_ALO 18432u
#define T_BHI 36864u
#define T_BLO 55296u

__global__ __launch_bounds__(256, 2) void stage2_mma(
    const float* __restrict__ b2p, float* __restrict__ out)
{
    extern __shared__ __nv_bfloat16 sm2[];
    const uint32_t sb = smem_u32(sm2);

    const int tid  = threadIdx.x;
    const int bhz  = blockIdx.z;
    const int mBase = blockIdx.y * 128;
    const int nBase = blockIdx.x * 128;

    // ---- async fills: four 128x64 bf16 tiles into stride-144B smem
    {
        const uint4* srcs[4] = {
            (const uint4*)(g_Xhi + (size_t)(bhz * Lq + mBase) * 64),
            (const uint4*)(g_Xlo + (size_t)(bhz * Lq + mBase) * 64),
            (const uint4*)(g_Yhi + (size_t)(bhz * Lq + nBase) * 64),
            (const uint4*)(g_Ylo + (size_t)(bhz * Lq + nBase) * 64)};
        const uint32_t dsts[4] = {T_AHI, T_ALO, T_BHI, T_BLO};
        #pragma unroll
        for (int t = 0; t < 4; ++t) {
            const uint4* s = srcs[t];
            uint32_t db = sb + dsts[t];
            #pragma unroll
            for (int i = 0; i < 4; ++i) {
                int idx = tid + i * 256;             // 1024 x 16B chunks
                int row = idx >> 3, c = idx & 7;
                CP16(db + (uint32_t)row * 144 + (uint32_t)c * 16, s + idx);
            }
        }
        CP_COMMIT();
    }

    // ---- per-lane ldmatrix addresses (while loads fly)
    const int wid = tid >> 5, lane = tid & 31;
    const int wm = (wid >> 2) * 64;
    const int wn = (wid & 3) * 32;
    const int g = lane >> 2, tg2 = (lane & 3) * 2;

    const uint32_t aoff =
        (uint32_t)(wm + (lane & 7) + ((lane >> 3) & 1) * 8) * 144 +
        (uint32_t)((lane >> 4) * 8) * 2;
    const uint32_t uaAhi = sb + T_AHI + aoff;
    const uint32_t uaAlo = sb + T_ALO + aoff;
    uint32_t uaBhi[2], uaBlo[2];
    #pragma unroll
    for (int p = 0; p < 2; ++p) {
        uint32_t boff =
            (uint32_t)(wn + p * 16 + (lane & 7) + ((lane >> 4) & 1) * 8) * 144 +
            (uint32_t)(((lane >> 3) & 1) * 8) * 2;
        uaBhi[p] = sb + T_BHI + boff;
        uaBlo[p] = sb + T_BLO + boff;
    }
    const float b2 = __ldg(b2p);

    float acc[4][4][4];
    #pragma unroll
    for (int mi = 0; mi < 4; ++mi)
        #pragma unroll
        for (int ni = 0; ni < 4; ++ni)
            #pragma unroll
            for (int q = 0; q < 4; ++q) acc[mi][ni][q] = 0.0f;

    CP_WAIT0();
    __syncthreads();

    #pragma unroll
    for (int ks = 0; ks < 4; ++ks) {
        const uint32_t kb = (uint32_t)ks * 32;       // 16 bf16 = 32 B
        uint32_t a[4][4], bh[2][4], bl[2][4];
        #pragma unroll
        for (int p = 0; p < 2; ++p) {
            ldm4(bh[p], uaBhi[p] + kb);
            ldm4(bl[p], uaBlo[p] + kb);
        }
        #pragma unroll
        for (int mi = 0; mi < 4; ++mi) ldm4(a[mi], uaAhi + mi * 2304u + kb);
        #pragma unroll
        for (int mi = 0; mi < 4; ++mi)
            #pragma unroll
            for (int ni = 0; ni < 4; ++ni) {
                mma_bf16(acc[mi][ni], a[mi], &bh[ni >> 1][(ni & 1) * 2]);
                mma_bf16(acc[mi][ni], a[mi], &bl[ni >> 1][(ni & 1) * 2]);
            }
        #pragma unroll
        for (int mi = 0; mi < 4; ++mi) ldm4(a[mi], uaAlo + mi * 2304u + kb);
        #pragma unroll
        for (int mi = 0; mi < 4; ++mi)
            #pragma unroll
            for (int ni = 0; ni < 4; ++ni)
                mma_bf16(acc[mi][ni], a[mi], &bh[ni >> 1][(ni & 1) * 2]);
    }

    // ---- epilogue: +b2, relu, float2 stores
    #pragma unroll
    for (int mi = 0; mi < 4; ++mi) {
        #pragma unroll
        for (int ni = 0; ni < 4; ++ni) {
            int r = mBase + wm + mi * 16 + g;
            int c = nBase + wn + ni * 8 + tg2;
            float* p = out + ((size_t)bhz * Lq + r) * Lq + c;
            float2 v0, v1;
            v0.x = fmaxf(acc[mi][ni][0] + b2, 0.0f);
            v0.y = fmaxf(acc[mi][ni][1] + b2, 0.0f);
            v1.x = fmaxf(acc[mi][ni][2] + b2, 0.0f);
            v1.y = fmaxf(acc[mi][ni][3] + b2, 0.0f);
            *(float2*)p            = v0;
            *(float2*)(p + 8 * Lq) = v1;
        }
    }
}

// ---------------------------------------------------------------------------
extern "C" void kernel_launch(void* const* d_in, const int* in_sizes, int n_in,
                              void* d_out, int out_size)
{
    const float* X  = (const float*)d_in[0];
    const float* Y  = (const float*)d_in[1];
    const float* W1 = (const float*)d_in[2];
    const float* b1 = (const float*)d_in[3];
    const float* w2 = (const float*)d_in[4];
    const float* b2 = (const float*)d_in[5];
    float* out = (float*)d_out;

    const int s1_smem = (2 * 128 * SA + 2 * 64 * SA) * 2 + 2 * 64 * 4;  // 55808
    cudaFuncSetAttribute(stage1_kernel,
                         cudaFuncAttributeMaxDynamicSharedMemorySize, s1_smem);
    stage1_kernel<<<dim3(BH * Lq / 128, 2, 1), 256, s1_smem>>>(X, Y, W1, b1, w2);

    const int s2_smem = 4 * 128 * SA * 2;                               // 73728
    cudaFuncSetAttribute(stage2_mma,
                         cudaFuncAttributeMaxDynamicSharedMemorySize, s2_smem);
    stage2_mma<<<dim3(8, 8, BH), 256, s2_smem>>>(b2, out);
}